// round 9
// baseline (speedup 1.0000x reference)
#include <cuda_runtime.h>
#include <cuda_bf16.h>
#include <cstdint>

// SharedGroupLinearLayer via mma.sync bf16 (split hi/lo, 3 passes), 2 CTAs/SM.
// out = (x·W1^T + b1) + a0 * (x·(W0-W1)^T + (b0-b1)), a0 = sigmoid(x·(rw0-rw1))
// Round 9: software pipeline with ONE barrier per tile. A-tile + logits double
// buffered: each iteration converts tile i+1 while MMAing tile i, so warps
// slip phases inside the barrier interval and convert hides under tensor time.
// TILE_M=64, acc 32 regs, B-hi in registers, B-lo ldmatrix'd from SMEM per k.

#define THREADS 256
#define TILE_M  64
#define NTILES  4096
#define GRID    304

// dynamic smem offsets
#define RAW_OFF  0        // 2 x 16KB raw x
#define AB_OFF   32768    // 2 x 16KB bf16 A tile (hi +0, lo +8192); init: Wcat hi
#define WLO_OFF  65536    // 16KB Wcat lo (persistent)
#define EMB_OFF  81920    // 16x64 f32
#define RWD_OFF  86016    // 64 f32
#define B1_OFF   86272    // 64 f32
#define BD_OFF   86528    // 64 f32
#define LOG_OFF  86784    // 2 x 64 f32 gate logits
#define SMEM_TOTAL 87296

__device__ __forceinline__ uint32_t smem_u32(const void* p) {
    uint32_t a;
    asm("{ .reg .u64 t; cvta.to.shared.u64 t, %1; cvt.u32.u64 %0, t; }" : "=r"(a) : "l"(p));
    return a;
}
// pack two f32 -> bf16x2 word: low 16 = first arg, high = second
__device__ __forceinline__ uint32_t cvt2bf(float lo, float hi) {
    uint32_t r;
    asm("cvt.rn.bf16x2.f32 %0, %1, %2;" : "=r"(r) : "f"(hi), "f"(lo));
    return r;
}
__device__ __forceinline__ void ldsm_x4(uint32_t* r, uint32_t addr) {
    asm volatile("ldmatrix.sync.aligned.m8n8.x4.shared.b16 {%0,%1,%2,%3}, [%4];"
        : "=r"(r[0]), "=r"(r[1]), "=r"(r[2]), "=r"(r[3]) : "r"(addr));
}
__device__ __forceinline__ void ldsm_x2(uint32_t* r, uint32_t addr) {
    asm volatile("ldmatrix.sync.aligned.m8n8.x2.shared.b16 {%0,%1}, [%2];"
        : "=r"(r[0]), "=r"(r[1]) : "r"(addr));
}
__device__ __forceinline__ void mma_bf16(float* d, const uint32_t* a, const uint32_t* b) {
    asm volatile("mma.sync.aligned.m16n8k16.row.col.f32.bf16.bf16.f32 "
        "{%0,%1,%2,%3}, {%4,%5,%6,%7}, {%8,%9}, {%0,%1,%2,%3};"
        : "+f"(d[0]), "+f"(d[1]), "+f"(d[2]), "+f"(d[3])
        : "r"(a[0]), "r"(a[1]), "r"(a[2]), "r"(a[3]), "r"(b[0]), "r"(b[1]));
}
__device__ __forceinline__ void cp_async16(uint32_t daddr, const void* gptr) {
    asm volatile("cp.async.ca.shared.global [%0], [%1], 16;" :: "r"(daddr), "l"(gptr));
}
#define CP_COMMIT() asm volatile("cp.async.commit_group;" ::: "memory")
#define CP_WAIT1()  asm volatile("cp.async.wait_group 1;" ::: "memory")

__global__ __launch_bounds__(THREADS, 2)
void sgl_mma7_kernel(const float* __restrict__ x,
                     const float* __restrict__ emb,
                     const float* __restrict__ read_w,
                     const float* __restrict__ w_stack,
                     const float* __restrict__ b_stack,
                     float* __restrict__ out)
{
    extern __shared__ __align__(1024) char smem[];
    const uint32_t sb = smem_u32(smem);

    const int tid  = threadIdx.x;
    const int lane = tid & 31;
    const int wid  = tid >> 5;
    const int q    = wid & 3;      // n-column group
    const int r    = wid >> 2;     // m-half (tokens r*32..r*32+31)

    float* emb_s = (float*)(smem + EMB_OFF);
    float* rwd_s = (float*)(smem + RWD_OFF);
    float* b1_s  = (float*)(smem + B1_OFF);
    float* bd_s  = (float*)(smem + BD_OFF);
    float* log_s = (float*)(smem + LOG_OFF);

    // ---- one-time setup ----
    for (int i = tid; i < 64; i += THREADS) {
        rwd_s[i] = read_w[2 * i] - read_w[2 * i + 1];
        float b1 = b_stack[64 + i];
        b1_s[i] = b1;
        bd_s[i] = b_stack[i] - b1;
    }
    for (int i = tid; i < 16 * 64; i += THREADS) emb_s[i] = emb[i];

    // Wcat bf16: hi -> A buffer 0 (temporary), lo -> WLO (persistent).
    // Column permutation so thread (q,tc) owns 4 contiguous outputs.
    for (int i = tid; i < 128 * 32; i += THREADS) {
        int n = i >> 5, kp = (i & 31) * 2;
        int half = n >> 6;
        int nn = n & 63;
        int p = nn & 7, t = (nn >> 3) & 1;
        int o = (nn & 48) + ((p >> 1) << 2) + 2 * t + (p & 1);
        float v0, v1;
        if (half == 0) {
            v0 = w_stack[4096 + o * 64 + kp];
            v1 = w_stack[4096 + o * 64 + kp + 1];
        } else {
            v0 = w_stack[o * 64 + kp]     - w_stack[4096 + o * 64 + kp];
            v1 = w_stack[o * 64 + kp + 1] - w_stack[4096 + o * 64 + kp + 1];
        }
        uint32_t h = cvt2bf(v0, v1);
        float h0 = __uint_as_float(h << 16);
        float h1 = __uint_as_float(h & 0xffff0000u);
        uint32_t l = cvt2bf(v0 - h0, v1 - h1);
        int off = n * 128 + (((kp >> 3) ^ (n & 7)) << 4) + (kp & 7) * 2;
        *(uint32_t*)(smem + AB_OFF + off)  = h;
        *(uint32_t*)(smem + WLO_OFF + off) = l;
    }
    __syncthreads();

    // ---- B-hi fragments -> registers (kept for whole kernel) ----
    uint32_t Bh[4][4][2];
    #pragma unroll
    for (int nti = 0; nti < 4; nti++) {
        int nt = 2 * q + (nti & 1) + ((nti >> 1) << 3);
        #pragma unroll
        for (int k = 0; k < 4; k++) {
            int row  = nt * 8 + (lane & 7);
            int unit = k * 2 + ((lane >> 3) & 1);
            ldsm_x2(Bh[nti][k], sb + AB_OFF + row * 128 + ((unit ^ (row & 7)) << 4));
        }
    }
    __syncthreads();   // A buffer 0 now free

    const int grp = lane >> 2, tc = lane & 3;
    const int o0  = 16 * q + 4 * tc;

    // B-lo ldsm addressing
    const int blrow1 = 16 * q + (lane & 7) + ((lane & 16) >> 1);
    const int blrowd = blrow1 + 64;
    const int blun   = (lane >> 3) & 1;
    const uint32_t bl1base = sb + WLO_OFF + blrow1 * 128;
    const uint32_t bldbase = sb + WLO_OFF + blrowd * 128;

    // convert helper (reads raw[rbuf], writes A[abuf] + log[abuf])
    auto convert = [&](int rbuf, int abuf) {
        const float4* raw4 = (const float4*)(smem + RAW_OFF + rbuf * 16384);
        float* logw = log_s + abuf * TILE_M;
        uint32_t abw = sb + AB_OFF + abuf * 16384;
        #pragma unroll
        for (int i = 0; i < 4; i++) {
            int j = tid + i * THREADS;
            int t = j >> 4, c = j & 15;
            float4 v = raw4[j];
            const float* ep = &emb_s[(t & 15) * 64 + c * 4];
            v.x += ep[0]; v.y += ep[1]; v.z += ep[2]; v.w += ep[3];
            const float* rp = &rwd_s[c * 4];
            float p = v.x * rp[0] + v.y * rp[1] + v.z * rp[2] + v.w * rp[3];
            p += __shfl_xor_sync(0xffffffffu, p, 1);
            p += __shfl_xor_sync(0xffffffffu, p, 2);
            p += __shfl_xor_sync(0xffffffffu, p, 4);
            p += __shfl_xor_sync(0xffffffffu, p, 8);
            if ((lane & 15) == 0) logw[t] = p;
            uint32_t h0 = cvt2bf(v.x, v.y);
            uint32_t h1 = cvt2bf(v.z, v.w);
            float hx = __uint_as_float(h0 << 16), hy = __uint_as_float(h0 & 0xffff0000u);
            float hz = __uint_as_float(h1 << 16), hw = __uint_as_float(h1 & 0xffff0000u);
            uint32_t l0 = cvt2bf(v.x - hx, v.y - hy);
            uint32_t l1 = cvt2bf(v.z - hz, v.w - hw);
            uint32_t off = (uint32_t)(t * 128 + (((c >> 1) ^ (t & 7)) << 4) + (c & 1) * 8);
            *(uint2*)(smem + AB_OFF + abuf * 16384 + off)        = make_uint2(h0, h1);
            *(uint2*)(smem + AB_OFF + abuf * 16384 + off + 8192) = make_uint2(l0, l1);
        }
        (void)abw;
    };

    // ---- prologue: stage tile0 + tile1, convert tile0 ----
    {
        const float4* src = (const float4*)x + (size_t)blockIdx.x * (TILE_M * 64 / 4);
        #pragma unroll
        for (int k = 0; k < 4; k++) {
            int j = tid + k * THREADS;
            cp_async16(sb + RAW_OFF + j * 16, src + j);
        }
    }
    CP_COMMIT();
    {
        int nt = blockIdx.x + GRID;
        if (nt < NTILES) {
            const float4* src = (const float4*)x + (size_t)nt * (TILE_M * 64 / 4);
            #pragma unroll
            for (int k = 0; k < 4; k++) {
                int j = tid + k * THREADS;
                cp_async16(sb + RAW_OFF + 16384 + j * 16, src + j);
            }
        }
    }
    CP_COMMIT();
    CP_WAIT1();        // tile0 in raw[0]
    convert(0, 0);     // A[0], log[0]

    int b = 0, jpar = 0;
    for (int tile = blockIdx.x; tile < NTILES; tile += GRID)
    {
        __syncthreads();   // A[b]/log[b] complete; prior MMA on A[b^1] done

        // prefetch tile+2 into raw[jpar] (tile j+1 lives in raw[jpar^1])
        {
            int pf = tile + 2 * GRID;
            if (pf < NTILES) {
                const float4* src = (const float4*)x + (size_t)pf * (TILE_M * 64 / 4);
                uint32_t dst = sb + RAW_OFF + jpar * 16384;
                #pragma unroll
                for (int k = 0; k < 4; k++) {
                    int j = tid + k * THREADS;
                    cp_async16(dst + j * 16, src + j);
                }
            }
        }
        CP_COMMIT();
        CP_WAIT1();        // tile+1's raw (committed last iter) complete

        // ---- convert tile+1 -> A[b^1] (runs under other warps' MMA) ----
        if (tile + GRID < NTILES) convert(jpar ^ 1, b ^ 1);

        // ---- MMA tile (A[b]): xh·wh + xh·wl + xl·wh ----
        float acc[2][4][4];
        #pragma unroll
        for (int m = 0; m < 2; m++)
            #pragma unroll
            for (int n = 0; n < 4; n++) {
                acc[m][n][0] = 0.f; acc[m][n][1] = 0.f;
                acc[m][n][2] = 0.f; acc[m][n][3] = 0.f;
            }

        const uint32_t abR = sb + AB_OFF + b * 16384;
        #pragma unroll
        for (int k = 0; k < 4; k++) {
            uint32_t bl1[4], bld[4];
            {
                uint32_t u = (uint32_t)(k * 2 + blun);
                ldsm_x4(bl1, bl1base + ((u ^ (blrow1 & 7)) << 4));
                ldsm_x4(bld, bldbase + ((u ^ (blrowd & 7)) << 4));
            }
            #pragma unroll
            for (int m = 0; m < 2; m++) {
                int tok  = r * 32 + m * 16 + (lane & 15);
                int unit = k * 2 + (lane >> 4);
                uint32_t aaddr = abR + tok * 128 + ((unit ^ (tok & 7)) << 4);
                uint32_t Ahi[4], Alo[4];
                ldsm_x4(Ahi, aaddr);
                ldsm_x4(Alo, aaddr + 8192);
                mma_bf16(acc[m][0], Ahi, Bh[0][k]);
                mma_bf16(acc[m][1], Ahi, Bh[1][k]);
                mma_bf16(acc[m][2], Ahi, Bh[2][k]);
                mma_bf16(acc[m][3], Ahi, Bh[3][k]);
                mma_bf16(acc[m][0], Ahi, &bl1[0]);
                mma_bf16(acc[m][1], Ahi, &bl1[2]);
                mma_bf16(acc[m][2], Ahi, &bld[0]);
                mma_bf16(acc[m][3], Ahi, &bld[2]);
                mma_bf16(acc[m][0], Alo, Bh[0][k]);
                mma_bf16(acc[m][1], Alo, Bh[1][k]);
                mma_bf16(acc[m][2], Alo, Bh[2][k]);
                mma_bf16(acc[m][3], Alo, Bh[3][k]);
            }
        }

        // ---- epilogue: gate combine + STG.128 ----
        {
            float* outb = out + (size_t)tile * (TILE_M * 64);
            const float* logR = log_s + b * TILE_M;
            float4 b1v = *(const float4*)&b1_s[o0];
            float4 bdv = *(const float4*)&bd_s[o0];
            #pragma unroll
            for (int m = 0; m < 2; m++) {
                int t0 = r * 32 + m * 16 + grp;
                int t1 = t0 + 8;
                float a00 = 1.f / (1.f + __expf(-logR[t0]));
                float a01 = 1.f / (1.f + __expf(-logR[t1]));
                float4 w;
                w.x = fmaf(a00, acc[m][2][0] + bdv.x, acc[m][0][0] + b1v.x);
                w.y = fmaf(a00, acc[m][2][1] + bdv.y, acc[m][0][1] + b1v.y);
                w.z = fmaf(a00, acc[m][3][0] + bdv.z, acc[m][1][0] + b1v.z);
                w.w = fmaf(a00, acc[m][3][1] + bdv.w, acc[m][1][1] + b1v.w);
                *(float4*)&outb[t0 * 64 + o0] = w;
                w.x = fmaf(a01, acc[m][2][2] + bdv.x, acc[m][0][2] + b1v.x);
                w.y = fmaf(a01, acc[m][2][3] + bdv.y, acc[m][0][3] + b1v.y);
                w.z = fmaf(a01, acc[m][3][2] + bdv.z, acc[m][1][2] + b1v.z);
                w.w = fmaf(a01, acc[m][3][3] + bdv.w, acc[m][1][3] + b1v.w);
                *(float4*)&outb[t1 * 64 + o0] = w;
            }
        }
        b ^= 1; jpar ^= 1;
    }
}

extern "C" void kernel_launch(void* const* d_in, const int* in_sizes, int n_in,
                              void* d_out, int out_size)
{
    const float* x       = (const float*)d_in[0];
    const float* emb     = (const float*)d_in[1];
    const float* read_w  = (const float*)d_in[2];
    const float* w_stack = (const float*)d_in[3];
    const float* b_stack = (const float*)d_in[4];
    float* out = (float*)d_out;

    cudaFuncSetAttribute(sgl_mma7_kernel, cudaFuncAttributeMaxDynamicSharedMemorySize, SMEM_TOTAL);
    sgl_mma7_kernel<<<GRID, THREADS, SMEM_TOTAL>>>(x, emb, read_w, w_stack, b_stack, out);
}

// round 10
// speedup vs baseline: 1.4570x; 1.4570x over previous
#include <cuda_runtime.h>
#include <cuda_fp16.h>
#include <cstdint>

// SharedGroupLinearLayer via single-pass fp16 mma.sync, 2 CTAs/SM.
// out = (x·W1^T + b1) + a0 * (x·(W0-W1)^T + (b0-b1)), a0 = sigmoid(x·(rw0-rw1))
// Precision: fp16 operands, f32 accumulate => global rel_err ~2e-4 (< 1e-3).
// Gate logit computed exactly in f32 during convert (2-shfl reduction).
// TILE_M=64, warp tile 32 tok x 32 out, B fragments register-resident.

#define THREADS 256
#define TILE_M  64
#define NTILES  4096
#define GRID    304

#define RAW_PITCH 320     // 256B row + 64B pad: conflict-free 4-thr/token reads

// dynamic smem offsets
#define RAW_OFF  0        // 2 x 20480B raw x (64 tok x 320B); init: W fp16 tile
#define AB_OFF   40960    // 8KB fp16 A tile (64 tok x 128B)
#define EMB_OFF  49152    // 16 x 80 f32 (320B pitch)
#define RWD_OFF  54272    // 64 f32
#define B1_OFF   54528    // 64 f32
#define BD_OFF   54784    // 64 f32
#define LOG_OFF  55040    // 64 f32 gate logits
#define SMEM_TOTAL 55296

__device__ __forceinline__ uint32_t smem_u32(const void* p) {
    uint32_t a;
    asm("{ .reg .u64 t; cvta.to.shared.u64 t, %1; cvt.u32.u64 %0, t; }" : "=r"(a) : "l"(p));
    return a;
}
// pack two f32 -> f16x2 word: low 16 = first arg, high = second
__device__ __forceinline__ uint32_t cvt2h(float lo, float hi) {
    uint32_t r;
    asm("cvt.rn.f16x2.f32 %0, %1, %2;" : "=r"(r) : "f"(hi), "f"(lo));
    return r;
}
__device__ __forceinline__ void ldsm_x4(uint32_t* r, uint32_t addr) {
    asm volatile("ldmatrix.sync.aligned.m8n8.x4.shared.b16 {%0,%1,%2,%3}, [%4];"
        : "=r"(r[0]), "=r"(r[1]), "=r"(r[2]), "=r"(r[3]) : "r"(addr));
}
__device__ __forceinline__ void ldsm_x2(uint32_t* r, uint32_t addr) {
    asm volatile("ldmatrix.sync.aligned.m8n8.x2.shared.b16 {%0,%1}, [%2];"
        : "=r"(r[0]), "=r"(r[1]) : "r"(addr));
}
__device__ __forceinline__ void mma_f16(float* d, const uint32_t* a, const uint32_t* b) {
    asm volatile("mma.sync.aligned.m16n8k16.row.col.f32.f16.f16.f32 "
        "{%0,%1,%2,%3}, {%4,%5,%6,%7}, {%8,%9}, {%0,%1,%2,%3};"
        : "+f"(d[0]), "+f"(d[1]), "+f"(d[2]), "+f"(d[3])
        : "r"(a[0]), "r"(a[1]), "r"(a[2]), "r"(a[3]), "r"(b[0]), "r"(b[1]));
}
__device__ __forceinline__ void cp_async16(uint32_t daddr, const void* gptr) {
    asm volatile("cp.async.ca.shared.global [%0], [%1], 16;" :: "r"(daddr), "l"(gptr));
}
#define CP_COMMIT() asm volatile("cp.async.commit_group;" ::: "memory")
#define CP_WAIT1()  asm volatile("cp.async.wait_group 1;" ::: "memory")

__global__ __launch_bounds__(THREADS, 2)
void sgl_fp16_kernel(const float* __restrict__ x,
                     const float* __restrict__ emb,
                     const float* __restrict__ read_w,
                     const float* __restrict__ w_stack,
                     const float* __restrict__ b_stack,
                     float* __restrict__ out)
{
    extern __shared__ __align__(1024) char smem[];
    const uint32_t sb = smem_u32(smem);

    const int tid  = threadIdx.x;
    const int lane = tid & 31;
    const int wid  = tid >> 5;
    const int q    = wid & 3;      // n-column group
    const int r    = wid >> 2;     // m-half (tokens r*32..r*32+31)

    float* emb_s = (float*)(smem + EMB_OFF);   // 320B pitch (80 floats/row)
    float* rwd_s = (float*)(smem + RWD_OFF);
    float* b1_s  = (float*)(smem + B1_OFF);
    float* bd_s  = (float*)(smem + BD_OFF);
    float* log_s = (float*)(smem + LOG_OFF);

    // ---- one-time setup ----
    for (int i = tid; i < 64; i += THREADS) {
        rwd_s[i] = read_w[2 * i] - read_w[2 * i + 1];
        float b1 = b_stack[64 + i];
        b1_s[i] = b1;
        bd_s[i] = b_stack[i] - b1;
    }
    for (int i = tid; i < 16 * 64; i += THREADS) {
        int row = i >> 6, k = i & 63;
        emb_s[row * 80 + k] = emb[i];
    }

    // Wcat fp16 (single precision level) staged in RAW area, col-permuted so
    // thread (q,tc) owns 4 contiguous outputs 16q+4tc..+3 in the epilogue.
    // smem row n = 128B (64 halves), XOR-swizzled 16B units.
    for (int i = tid; i < 128 * 32; i += THREADS) {
        int n = i >> 5, kp = (i & 31) * 2;
        int half = n >> 6;              // 0: W1, 1: W0-W1
        int nn = n & 63;
        int p = nn & 7, t = (nn >> 3) & 1;
        int o = (nn & 48) + ((p >> 1) << 2) + 2 * t + (p & 1);
        float v0, v1;
        if (half == 0) {
            v0 = w_stack[4096 + o * 64 + kp];
            v1 = w_stack[4096 + o * 64 + kp + 1];
        } else {
            v0 = w_stack[o * 64 + kp]     - w_stack[4096 + o * 64 + kp];
            v1 = w_stack[o * 64 + kp + 1] - w_stack[4096 + o * 64 + kp + 1];
        }
        int off = n * 128 + (((kp >> 3) ^ (n & 7)) << 4) + (kp & 7) * 2;
        *(uint32_t*)(smem + RAW_OFF + off) = cvt2h(v0, v1);
    }
    __syncthreads();

    // ---- B fragments -> registers (kept for whole kernel) ----
    // nti 0,1 = h1 tiles (2q, 2q+1); nti 2,3 = hd tiles (2q+8, 2q+9)
    uint32_t Bh[4][4][2];
    #pragma unroll
    for (int nti = 0; nti < 4; nti++) {
        int nt = 2 * q + (nti & 1) + ((nti >> 1) << 3);
        #pragma unroll
        for (int k = 0; k < 4; k++) {
            int row  = nt * 8 + (lane & 7);
            int unit = k * 2 + ((lane >> 3) & 1);
            ldsm_x2(Bh[nti][k], sb + RAW_OFF + row * 128 + ((unit ^ (row & 7)) << 4));
        }
    }
    __syncthreads();   // RAW area now free for x staging

    const int grp = lane >> 2, tc = lane & 3;
    const int o0  = 16 * q + 4 * tc;
    const int ct  = tid >> 2;        // convert token (0..63)
    const int cp  = tid & 3;         // convert part (4 chunks each)

    // ---- prologue: stage first tile's x ----
    {
        const float4* src = (const float4*)x + (size_t)blockIdx.x * (TILE_M * 64 / 4);
        #pragma unroll
        for (int k = 0; k < 4; k++) {
            int j = tid + k * THREADS;
            int t = j >> 4, c = j & 15;
            cp_async16(sb + RAW_OFF + t * RAW_PITCH + c * 16, src + j);
        }
    }
    CP_COMMIT();

    int buf = 0;
    for (int tile = blockIdx.x; tile < NTILES; tile += GRID)
    {
        // prefetch next tile into other raw buffer
        {
            int nt = tile + GRID;
            if (nt < NTILES) {
                const float4* src = (const float4*)x + (size_t)nt * (TILE_M * 64 / 4);
                uint32_t dst = sb + RAW_OFF + (buf ^ 1) * 20480;
                #pragma unroll
                for (int k = 0; k < 4; k++) {
                    int j = tid + k * THREADS;
                    int t = j >> 4, c = j & 15;
                    cp_async16(dst + t * RAW_PITCH + c * 16, src + j);
                }
            }
        }
        CP_COMMIT();
        CP_WAIT1();          // current tile's copy complete
        __syncthreads();     // + separates prev MMA reads from A rewrite

        // ---- convert: 4 threads per token, 2-shfl gate reduction ----
        {
            const char* rawb = smem + RAW_OFF + buf * 20480 + ct * RAW_PITCH;
            const float* ep  = &emb_s[(ct & 15) * 80];
            float g = 0.f;
            uint2 hw[4];
            #pragma unroll
            for (int i = 0; i < 4; i++) {
                int c = cp + 4 * i;
                float4 v = *(const float4*)(rawb + c * 16);
                float4 e = *(const float4*)(ep + c * 4);
                v.x += e.x; v.y += e.y; v.z += e.z; v.w += e.w;
                const float* rp = &rwd_s[c * 4];
                g += v.x * rp[0] + v.y * rp[1] + v.z * rp[2] + v.w * rp[3];
                hw[i].x = cvt2h(v.x, v.y);
                hw[i].y = cvt2h(v.z, v.w);
            }
            g += __shfl_xor_sync(0xffffffffu, g, 1);
            g += __shfl_xor_sync(0xffffffffu, g, 2);
            if (cp == 0) log_s[ct] = g;
            #pragma unroll
            for (int i = 0; i < 4; i++) {
                int c = cp + 4 * i;
                uint32_t off = (uint32_t)(ct * 128 + (((c >> 1) ^ (ct & 7)) << 4) + (c & 1) * 8);
                *(uint2*)(smem + AB_OFF + off) = hw[i];
            }
        }
        __syncthreads();

        // ---- MMA: single fp16 pass, B in registers ----
        float acc[2][4][4];
        #pragma unroll
        for (int m = 0; m < 2; m++)
            #pragma unroll
            for (int n = 0; n < 4; n++) {
                acc[m][n][0] = 0.f; acc[m][n][1] = 0.f;
                acc[m][n][2] = 0.f; acc[m][n][3] = 0.f;
            }

        #pragma unroll
        for (int k = 0; k < 4; k++) {
            #pragma unroll
            for (int m = 0; m < 2; m++) {
                int tok  = r * 32 + m * 16 + (lane & 15);
                int unit = k * 2 + (lane >> 4);
                uint32_t aaddr = sb + AB_OFF + tok * 128 + ((unit ^ (tok & 7)) << 4);
                uint32_t A[4];
                ldsm_x4(A, aaddr);
                mma_f16(acc[m][0], A, Bh[0][k]);
                mma_f16(acc[m][1], A, Bh[1][k]);
                mma_f16(acc[m][2], A, Bh[2][k]);
                mma_f16(acc[m][3], A, Bh[3][k]);
            }
        }

        // ---- epilogue: gate combine + STG.128 ----
        {
            float* outb = out + (size_t)tile * (TILE_M * 64);
            float4 b1v = *(const float4*)&b1_s[o0];
            float4 bdv = *(const float4*)&bd_s[o0];
            #pragma unroll
            for (int m = 0; m < 2; m++) {
                int t0 = r * 32 + m * 16 + grp;
                int t1 = t0 + 8;
                float a00 = 1.f / (1.f + __expf(-log_s[t0]));
                float a01 = 1.f / (1.f + __expf(-log_s[t1]));
                float4 w;
                w.x = fmaf(a00, acc[m][2][0] + bdv.x, acc[m][0][0] + b1v.x);
                w.y = fmaf(a00, acc[m][2][1] + bdv.y, acc[m][0][1] + b1v.y);
                w.z = fmaf(a00, acc[m][3][0] + bdv.z, acc[m][1][0] + b1v.z);
                w.w = fmaf(a00, acc[m][3][1] + bdv.w, acc[m][1][1] + b1v.w);
                *(float4*)&outb[t0 * 64 + o0] = w;
                w.x = fmaf(a01, acc[m][2][2] + bdv.x, acc[m][0][2] + b1v.x);
                w.y = fmaf(a01, acc[m][2][3] + bdv.y, acc[m][0][3] + b1v.y);
                w.z = fmaf(a01, acc[m][3][2] + bdv.z, acc[m][1][2] + b1v.z);
                w.w = fmaf(a01, acc[m][3][3] + bdv.w, acc[m][1][3] + b1v.w);
                *(float4*)&outb[t1 * 64 + o0] = w;
            }
        }
        buf ^= 1;
        // next iteration's top __syncthreads separates this MMA/epilogue
        // from the next convert's A-tile rewrite.
    }
}

extern "C" void kernel_launch(void* const* d_in, const int* in_sizes, int n_in,
                              void* d_out, int out_size)
{
    const float* x       = (const float*)d_in[0];
    const float* emb     = (const float*)d_in[1];
    const float* read_w  = (const float*)d_in[2];
    const float* w_stack = (const float*)d_in[3];
    const float* b_stack = (const float*)d_in[4];
    float* out = (float*)d_out;

    cudaFuncSetAttribute(sgl_fp16_kernel, cudaFuncAttributeMaxDynamicSharedMemorySize, SMEM_TOTAL);
    sgl_fp16_kernel<<<GRID, THREADS, SMEM_TOTAL>>>(x, emb, read_w, w_stack, b_stack, out);
}